// round 7
// baseline (speedup 1.0000x reference)
#include <cuda_runtime.h>
#include <cuda_bf16.h>

// GCN 2-layer regression on GB300. N=100000 nodes, E=3.2M edges, d_in=128, h=16.
//
// Bucketed-CSR gather formulation (no float atomics, no scan, self-resetting):
//   each node owns 128 CSR slots; one edge pass fills buckets with atomic cursors.
//   deg[d] = indegree(d) + 1 (self loop);  dis = rsqrt(deg)
//   xws1 = dis * (x @ W1)
//   h1[d] = dis[d] * (xws1[d] + sum_nbr xws1[s])   -> fused relu+b1, @W2, *dis -> xws2
//   h2[d] = dis[d] * (xws2[d] + sum_nbr xws2[s])   -> fused relu+b2, .Wl + bl -> out
// g_cnt is zeroed in gather2's epilogue, so no separate zero pass is needed:
// device globals start zeroed, and every run leaves them zeroed.

#define MAXN 100000
#define CAP  128            // per-node bucket capacity (Poisson(32) max deg ~65)

__device__ float4 g_xw [MAXN * 4];     // layer-1 dis-scaled features
__device__ float4 g_xw2[MAXN * 4];     // layer-2 dis-scaled features
__device__ float  g_dis[MAXN];         // deg^{-1/2}
__device__ int    g_cnt[MAXN];         // indegree counts / fill cursors (self-reset)
__device__ int    g_csr[MAXN * CAP];   // bucketed src ids

// ---------------------------------------------------------------------------
// Bucket fill, 8 edges per thread with vector loads. Per-block dtype detect:
// int64 values < 2^31 -> every odd 32-bit word is 0; random int32 ids aren't.
__global__ void fill_kernel(const void* __restrict__ ei, long long E) {
    __shared__ int s_is64;
    if (threadIdx.x == 0) {
        const int* w = (const int*)ei;
        int az = 1;
        for (int k = 0; k < 64; k++)
            if (w[2 * k + 1] != 0) { az = 0; break; }
        s_is64 = az;
    }
    __syncthreads();
    const int is64 = s_is64;

    long long q  = (long long)blockIdx.x * blockDim.x + threadIdx.x;
    long long e0 = q * 8;
    if (e0 >= E) return;

    int s[8], d[8];
    int n;
    if (e0 + 8 <= E && (E & 1) == 0) {
        n = 8;
        if (is64) {
            const longlong2* sp = (const longlong2*)ei;
            const longlong2* dp = (const longlong2*)((const long long*)ei + E);
#pragma unroll
            for (int k = 0; k < 4; k++) {
                longlong2 a = sp[q * 4 + k];
                s[2 * k] = (int)a.x; s[2 * k + 1] = (int)a.y;
            }
#pragma unroll
            for (int k = 0; k < 4; k++) {
                longlong2 a = dp[q * 4 + k];
                d[2 * k] = (int)a.x; d[2 * k + 1] = (int)a.y;
            }
        } else if ((E & 3) == 0) {
            const int4* sp = (const int4*)ei;
            const int4* dp = (const int4*)((const int*)ei + E);
#pragma unroll
            for (int k = 0; k < 2; k++) {
                int4 a = sp[q * 2 + k];
                s[4 * k] = a.x; s[4 * k + 1] = a.y; s[4 * k + 2] = a.z; s[4 * k + 3] = a.w;
            }
#pragma unroll
            for (int k = 0; k < 2; k++) {
                int4 a = dp[q * 2 + k];
                d[4 * k] = a.x; d[4 * k + 1] = a.y; d[4 * k + 2] = a.z; d[4 * k + 3] = a.w;
            }
        } else {
            const int* w = (const int*)ei;
#pragma unroll
            for (int k = 0; k < 8; k++) { s[k] = w[e0 + k]; d[k] = w[E + e0 + k]; }
        }
    } else {
        n = (int)(E - e0 < 8 ? E - e0 : 8);
        for (int k = 0; k < n; k++) {
            if (is64) {
                s[k] = (int)((const long long*)ei)[e0 + k];
                d[k] = (int)((const long long*)ei)[E + e0 + k];
            } else {
                s[k] = ((const int*)ei)[e0 + k];
                d[k] = ((const int*)ei)[E + e0 + k];
            }
        }
    }

    // batch the return-atomics (8 outstanding), then the dependent stores
    int pos[8];
#pragma unroll
    for (int k = 0; k < 8; k++)
        if (k < n) pos[k] = atomicAdd(&g_cnt[d[k]], 1);
#pragma unroll
    for (int k = 0; k < 8; k++)
        if (k < n) g_csr[((size_t)d[k] << 7) + pos[k]] = s[k];
}

// ---------------------------------------------------------------------------
// GEMM1: g_xw = dis * (x @ W1); also computes and stores dis = rsqrt(cnt+1).
// 256 threads / 32 nodes per block.
__global__ void gemm1_kernel(const float* __restrict__ x,
                             const float* __restrict__ W1, int N) {
    __shared__ float xs[32 * 132];   // padded against bank conflicts
    __shared__ float ws[128 * 16];
    const int tid  = threadIdx.x;
    const int base = blockIdx.x * 32;

    for (int i = tid; i < 128 * 16; i += 256) ws[i] = W1[i];

    const int rows = min(32, N - base);
    const float4* xg = (const float4*)(x + (size_t)base * 128);
    for (int i = tid; i < rows * 32; i += 256) {
        float4 v = xg[i];
        int r = i >> 5, c = (i & 31) * 4;
        float* p = xs + r * 132 + c;
        p[0] = v.x; p[1] = v.y; p[2] = v.z; p[3] = v.w;
    }
    __syncthreads();

    const int node = tid >> 3;      // 0..31
    const int j0   = tid & 7;       // handles cols j0 and j0+8
    if (base + node >= N) return;

    const float* xr = xs + node * 132;
    float a0 = 0.f, a1 = 0.f;
#pragma unroll
    for (int k = 0; k < 128; k++) {
        float xv = xr[k];
        a0 = fmaf(xv, ws[k * 16 + j0],     a0);
        a1 = fmaf(xv, ws[k * 16 + j0 + 8], a1);
    }
    const int n = base + node;
    float dv = rsqrtf((float)(g_cnt[n] + 1));
    if (j0 == 0) g_dis[n] = dv;      // one writer per node
    float* xwp = (float*)g_xw + (size_t)n * 16;
    xwp[j0]     = a0 * dv;
    xwp[j0 + 8] = a1 * dv;
}

// ---------------------------------------------------------------------------
// Quad-cooperative neighbor sum: thread j of the quad owns float4 column j
// of the node's 16-float row. Returns dis[node] * (self + sum of neighbors).
// Unrolled x8 for memory-level parallelism (8 in-flight LDG.128).
__device__ __forceinline__ float4 gather_sum(const float4* __restrict__ feat,
                                             int node, int j, int cnt) {
    const int beg = node << 7;           // bucket base (512B aligned)

    float4 self = __ldg(feat + (size_t)node * 4 + j);
    float ax = self.x, ay = self.y, az = self.z, aw = self.w;

    int k = 0;
    for (; k + 8 <= cnt; k += 8) {
        int4 sa = *(const int4*)&g_csr[beg + k];
        int4 sb = *(const int4*)&g_csr[beg + k + 4];
        float4 v0 = __ldg(feat + (size_t)sa.x * 4 + j);
        float4 v1 = __ldg(feat + (size_t)sa.y * 4 + j);
        float4 v2 = __ldg(feat + (size_t)sa.z * 4 + j);
        float4 v3 = __ldg(feat + (size_t)sa.w * 4 + j);
        float4 v4 = __ldg(feat + (size_t)sb.x * 4 + j);
        float4 v5 = __ldg(feat + (size_t)sb.y * 4 + j);
        float4 v6 = __ldg(feat + (size_t)sb.z * 4 + j);
        float4 v7 = __ldg(feat + (size_t)sb.w * 4 + j);
        ax += ((v0.x + v1.x) + (v2.x + v3.x)) + ((v4.x + v5.x) + (v6.x + v7.x));
        ay += ((v0.y + v1.y) + (v2.y + v3.y)) + ((v4.y + v5.y) + (v6.y + v7.y));
        az += ((v0.z + v1.z) + (v2.z + v3.z)) + ((v4.z + v5.z) + (v6.z + v7.z));
        aw += ((v0.w + v1.w) + (v2.w + v3.w)) + ((v4.w + v5.w) + (v6.w + v7.w));
    }
    if (k + 4 <= cnt) {
        int4 sa = *(const int4*)&g_csr[beg + k];
        float4 v0 = __ldg(feat + (size_t)sa.x * 4 + j);
        float4 v1 = __ldg(feat + (size_t)sa.y * 4 + j);
        float4 v2 = __ldg(feat + (size_t)sa.z * 4 + j);
        float4 v3 = __ldg(feat + (size_t)sa.w * 4 + j);
        ax += (v0.x + v1.x) + (v2.x + v3.x);
        ay += (v0.y + v1.y) + (v2.y + v3.y);
        az += (v0.z + v1.z) + (v2.z + v3.z);
        aw += (v0.w + v1.w) + (v2.w + v3.w);
        k += 4;
    }
    for (; k < cnt; k++) {
        int s = g_csr[beg + k];
        float4 v = __ldg(feat + (size_t)s * 4 + j);
        ax += v.x; ay += v.y; az += v.z; aw += v.w;
    }

    float dd = g_dis[node];
    return make_float4(ax * dd, ay * dd, az * dd, aw * dd);
}

// Gather layer 1 fused with layer-2 transform:
//   h1 = gather(g_xw); t = relu(h1+b1); g_xw2 = dis * (t @ W2)
__global__ void gather1_kernel(const float* __restrict__ W2,
                               const float* __restrict__ b1, int N) {
    __shared__ float4 ws4[16 * 4];   // W2 row k as 4 float4
    __shared__ float  bs[16];
    const int tid = threadIdx.x;
    if (tid < 64) ws4[tid] = ((const float4*)W2)[tid];
    if (tid < 16) bs[tid]  = b1[tid];
    __syncthreads();

    int t = blockIdx.x * blockDim.x + tid;
    int node = t >> 2;
    bool valid = node < N;
    if (!valid) node = 0;            // keep quad alive for shuffles
    const int j    = t & 3;
    const int lane = tid & 31;

    float4 h = gather_sum(g_xw, node, j, g_cnt[node]);

    // relu + bias on my 4 components
    float tj[4];
    tj[0] = fmaxf(h.x + bs[j * 4 + 0], 0.f);
    tj[1] = fmaxf(h.y + bs[j * 4 + 1], 0.f);
    tj[2] = fmaxf(h.z + bs[j * 4 + 2], 0.f);
    tj[3] = fmaxf(h.w + bs[j * 4 + 3], 0.f);

    // exchange full 16-vector within the quad
    float tf[16];
    const int qbase = lane & ~3;
#pragma unroll
    for (int k = 0; k < 16; k++)
        tf[k] = __shfl_sync(0xFFFFFFFFu, tj[k & 3], qbase + (k >> 2));

    // my 4 output columns: acc[c] = sum_k tf[k] * W2[k][4j+c]
    float4 acc = make_float4(0.f, 0.f, 0.f, 0.f);
#pragma unroll
    for (int k = 0; k < 16; k++) {
        float4 w = ws4[k * 4 + j];
        acc.x = fmaf(tf[k], w.x, acc.x);
        acc.y = fmaf(tf[k], w.y, acc.y);
        acc.z = fmaf(tf[k], w.z, acc.z);
        acc.w = fmaf(tf[k], w.w, acc.w);
    }

    if (valid) {
        float dv = g_dis[node];
        g_xw2[(size_t)node * 4 + j] =
            make_float4(acc.x * dv, acc.y * dv, acc.z * dv, acc.w * dv);
    }
}

// Gather layer 2 fused with the output head:
//   h2 = gather(g_xw2); out = relu(h2+b2) . Wl + bl
// Epilogue: resets g_cnt[node] to 0 for the next run (self-resetting state).
__global__ void gather2_kernel(const float* __restrict__ b2,
                               const float* __restrict__ Wl,
                               const float* __restrict__ bl,
                               float* __restrict__ out, int N) {
    __shared__ float bs[16];
    __shared__ float wl[16];
    __shared__ float bl0;
    const int tid = threadIdx.x;
    if (tid < 16) { bs[tid] = b2[tid]; wl[tid] = Wl[tid]; }
    if (tid == 0) bl0 = bl[0];
    __syncthreads();

    int t = blockIdx.x * blockDim.x + tid;
    int node = t >> 2;
    bool valid = node < N;
    if (!valid) node = 0;
    const int j = t & 3;

    int cnt = g_cnt[node];
    float4 h = gather_sum(g_xw2, node, j, cnt);

    float s = fmaxf(h.x + bs[j * 4 + 0], 0.f) * wl[j * 4 + 0]
            + fmaxf(h.y + bs[j * 4 + 1], 0.f) * wl[j * 4 + 1]
            + fmaxf(h.z + bs[j * 4 + 2], 0.f) * wl[j * 4 + 2]
            + fmaxf(h.w + bs[j * 4 + 3], 0.f) * wl[j * 4 + 3];

    // quad reduction
    s += __shfl_xor_sync(0xFFFFFFFFu, s, 1);
    s += __shfl_xor_sync(0xFFFFFFFFu, s, 2);

    if (valid && j == 0) {
        out[node] = s + bl0;
        g_cnt[node] = 0;             // reset for next launch (after last read)
    }
}

// ---------------------------------------------------------------------------
extern "C" void kernel_launch(void* const* d_in, const int* in_sizes, int n_in,
                              void* d_out, int out_size) {
    const float* x  = (const float*)d_in[0];
    const void*  ei = d_in[1];
    const float* W1 = (const float*)d_in[2];
    const float* b1 = (const float*)d_in[3];
    const float* W2 = (const float*)d_in[4];
    const float* b2 = (const float*)d_in[5];
    const float* Wl = (const float*)d_in[6];
    const float* bl = (const float*)d_in[7];
    float* out = (float*)d_out;

    const int       N = in_sizes[0] / 128;
    const long long E = (long long)in_sizes[1] / 2;

    const int fillBlocks   = (int)(((E + 7) / 8 + 255) / 256);
    const int gemmBlocks   = (N + 31) / 32;
    const int gatherBlocks = (N * 4 + 255) / 256;

    fill_kernel<<<fillBlocks, 256>>>(ei, E);                    // bucket CSR + counts
    gemm1_kernel<<<gemmBlocks, 256>>>(x, W1, N);                // dis + g_xw
    gather1_kernel<<<gatherBlocks, 256>>>(W2, b1, N);           // g_xw2
    gather2_kernel<<<gatherBlocks, 256>>>(b2, Wl, bl, out, N);  // out (+ cnt reset)
}